// round 6
// baseline (speedup 1.0000x reference)
#include <cuda_runtime.h>
#include <cooperative_groups.h>
#include <cstdint>

namespace cg = cooperative_groups;

// VariableGroupNorm: x[N,C,H,W] fp32, ragged groups (channels contiguous per group).
// N=32, C=256, H=W=56, G=32. Group sizes alternate 4/12 -> each adjacent PAIR of
// groups is 16 channels. A 2-CTA cluster owns one (n, pair); each CTA caches its
// 8 channels (100 KB) in SMEM, so x is read from DRAM exactly once.
// Stats cross the 2 CTAs via DSMEM partial exchange + cluster.sync.

#define NB 32
#define CC 256
#define GG 32
#define HW 3136                 // 56*56
#define HW4 784                 // float4 per channel
#define SUB_NV (4 * HW4)        // float4 per 4-channel subchunk = 3136
#define CTA_NV (2 * SUB_NV)     // float4 per CTA (8 channels) = 6272
#define TPB 512
#define SMEM_BYTES (CTA_NV * 16)  // 100352 bytes
#define VGN_EPS 1e-5f

// Decode sizes of groups 2p and 2p+1 (int32 or int64, defensively).
__device__ __forceinline__ void decode_pair_sizes(const void* __restrict__ gs_raw,
                                                  int p, int& gsA, int& gsB) {
    const int* p32 = (const int*)gs_raw;
    long long s32 = 0;
    #pragma unroll
    for (int i = 0; i < GG; i++) s32 += __ldg(&p32[i]);
    const bool is32 = (s32 == (long long)CC);
    const long long* p64 = (const long long*)gs_raw;
    gsA = is32 ? __ldg(&p32[2 * p])     : (int)__ldg(&p64[2 * p]);
    gsB = is32 ? __ldg(&p32[2 * p + 1]) : (int)__ldg(&p64[2 * p + 1]);
}

__global__ void __cluster_dims__(2, 1, 1) __launch_bounds__(TPB)
vgn_fused(const float* __restrict__ x,
          const float* __restrict__ gamma,
          const float* __restrict__ beta,
          float* __restrict__ out,
          const void* __restrict__ gs_raw) {
    extern __shared__ float4 smem[];                 // 6272 float4 tile cache
    __shared__ float4 shw[TPB / 32];                 // warp partials (s0,ss0,s1,ss1)
    __shared__ float2 part_self[2];                  // this CTA's 2 subchunk partials
    __shared__ float2 sh_prm[2];                     // (scale, shift) per subchunk

    cg::cluster_group clu = cg::this_cluster();
    const int rank = (int)clu.block_rank();          // 0 or 1
    const int item = blockIdx.x >> 1;                // (n, pair) id
    const int n = item & (NB - 1);
    const int p = item >> 5;
    const int c0 = p * 16 + rank * 8;                // first channel of this CTA

    const size_t base = ((size_t)n * CC + (size_t)c0) * HW;
    const float4* __restrict__ px = (const float4*)(x + base);
    float4* __restrict__ po       = (float4*)(out + base);

    // ---- phase 1: single DRAM read -> SMEM, accumulate per-subchunk stats ----
    float s0 = 0.f, ss0 = 0.f, s1 = 0.f, ss1 = 0.f;
    for (int i = threadIdx.x; i < SUB_NV; i += TPB) {
        const float4 v = __ldcs(px + i);
        smem[i] = v;
        s0  += (v.x + v.y) + (v.z + v.w);
        ss0 += v.x * v.x + v.y * v.y + v.z * v.z + v.w * v.w;
    }
    for (int i = threadIdx.x; i < SUB_NV; i += TPB) {
        const float4 v = __ldcs(px + SUB_NV + i);
        smem[SUB_NV + i] = v;
        s1  += (v.x + v.y) + (v.z + v.w);
        ss1 += v.x * v.x + v.y * v.y + v.z * v.z + v.w * v.w;
    }

    // ---- block reduce 4 values across 16 warps ----
    #pragma unroll
    for (int o = 16; o > 0; o >>= 1) {
        s0  += __shfl_xor_sync(0xFFFFFFFFu, s0,  o);
        ss0 += __shfl_xor_sync(0xFFFFFFFFu, ss0, o);
        s1  += __shfl_xor_sync(0xFFFFFFFFu, s1,  o);
        ss1 += __shfl_xor_sync(0xFFFFFFFFu, ss1, o);
    }
    const int wid = threadIdx.x >> 5, lid = threadIdx.x & 31;
    if (lid == 0) shw[wid] = make_float4(s0, ss0, s1, ss1);
    __syncthreads();
    if (threadIdx.x == 0) {
        float t0 = 0.f, u0 = 0.f, t1 = 0.f, u1 = 0.f;
        #pragma unroll
        for (int w = 0; w < TPB / 32; w++) {
            t0 += shw[w].x; u0 += shw[w].y;
            t1 += shw[w].z; u1 += shw[w].w;
        }
        part_self[0] = make_float2(t0, u0);
        part_self[1] = make_float2(t1, u1);
    }

    // ---- cluster exchange: 4 subchunk partials -> 2 group params ----
    clu.sync();                                      // partials visible cluster-wide
    if (threadIdx.x == 0) {
        int gsA, gsB;
        decode_pair_sizes(gs_raw, p, gsA, gsB);
        const int nA = gsA >> 2;                     // subchunks in group A (of 4)

        // Gather all 4 subchunk partials (global subchunk q = r*2 + j).
        float2 q[4];
        #pragma unroll
        for (int r = 0; r < 2; r++) {
            const float2* pr = (const float2*)clu.map_shared_rank((void*)part_self, r);
            q[r * 2 + 0] = pr[0];
            q[r * 2 + 1] = pr[1];
        }
        float tsA = 0.f, tssA = 0.f, tsB = 0.f, tssB = 0.f;
        #pragma unroll
        for (int k = 0; k < 4; k++) {
            if (k < nA) { tsA += q[k].x; tssA += q[k].y; }
            else        { tsB += q[k].x; tssB += q[k].y; }
        }
        const int gA = 2 * p, gB = gA + 1;
        const float invA  = 1.0f / (float)(gsA * HW);
        const float meanA = tsA * invA;
        const float varA  = tssA * invA - meanA * meanA;
        const float scA   = __ldg(&gamma[gA]) * rsqrtf(varA + VGN_EPS);
        const float sfA   = fmaf(-meanA, scA, __ldg(&beta[gA]));
        const float invB  = 1.0f / (float)(gsB * HW);
        const float meanB = tsB * invB;
        const float varB  = tssB * invB - meanB * meanB;
        const float scB   = __ldg(&gamma[gB]) * rsqrtf(varB + VGN_EPS);
        const float sfB   = fmaf(-meanB, scB, __ldg(&beta[gB]));

        // My two subchunks are global q = rank*2, rank*2+1.
        const int q0 = rank * 2, q1 = q0 + 1;
        sh_prm[0] = (q0 < nA) ? make_float2(scA, sfA) : make_float2(scB, sfB);
        sh_prm[1] = (q1 < nA) ? make_float2(scA, sfA) : make_float2(scB, sfB);
    }
    clu.sync();                                      // params ready; peers done reading
    const float2 prm0 = sh_prm[0];
    const float2 prm1 = sh_prm[1];

    // ---- phase 2: apply from SMEM, single DRAM write ----
    for (int i = threadIdx.x; i < SUB_NV; i += TPB) {
        float4 v = smem[i];
        v.x = fmaf(v.x, prm0.x, prm0.y);
        v.y = fmaf(v.y, prm0.x, prm0.y);
        v.z = fmaf(v.z, prm0.x, prm0.y);
        v.w = fmaf(v.w, prm0.x, prm0.y);
        __stcs(po + i, v);
    }
    for (int i = threadIdx.x; i < SUB_NV; i += TPB) {
        float4 v = smem[SUB_NV + i];
        v.x = fmaf(v.x, prm1.x, prm1.y);
        v.y = fmaf(v.y, prm1.x, prm1.y);
        v.z = fmaf(v.z, prm1.x, prm1.y);
        v.w = fmaf(v.w, prm1.x, prm1.y);
        __stcs(po + SUB_NV + i, v);
    }
}

extern "C" void kernel_launch(void* const* d_in, const int* in_sizes, int n_in,
                              void* d_out, int out_size) {
    const float* x     = (const float*)d_in[0];
    const float* gamma = (const float*)d_in[1];
    const float* beta  = (const float*)d_in[2];
    const void*  gsz   = d_in[3];
    float* out = (float*)d_out;

    // Idempotent; required for >48KB dynamic smem.
    cudaFuncSetAttribute(vgn_fused, cudaFuncAttributeMaxDynamicSharedMemorySize,
                         SMEM_BYTES);

    vgn_fused<<<NB * (GG / 2) * 2, TPB, SMEM_BYTES>>>(x, gamma, beta, out, gsz);
}

// round 8
// speedup vs baseline: 1.0621x; 1.0621x over previous
#include <cuda_runtime.h>
#include <cstdint>

// VariableGroupNorm: x[N,C,H,W] fp32, ragged groups (channels contiguous per group).
// N=32, C=256, H=W=56, G=32. Sizes alternate 4/12 (even groups small, odd big).
// Balanced fused kernel: per sample n, 16 "big" CTAs (one 12-ch group each) and
// 8 "small" CTAs (two 4-ch groups each). 768 CTAs total, all co-resident.

#define NB 32
#define CC 256
#define GG 32
#define HW 3136                 // 56*56
#define HW4 784                 // float4 per channel
#define VGN_EPS 1e-5f
#define TPB 256
#define NWARP (TPB / 32)

// Decode group start/size table (int32 or int64, defensively).
__device__ __forceinline__ void decode_group(const void* __restrict__ gs_raw,
                                             int g, int& start, int& size) {
    const int* p32 = (const int*)gs_raw;
    long long s32 = 0;
    #pragma unroll
    for (int i = 0; i < GG; i++) s32 += __ldg(&p32[i]);
    const bool is32 = (s32 == (long long)CC);
    const long long* p64 = (const long long*)gs_raw;
    int st = 0, sz = 0;
    #pragma unroll
    for (int i = 0; i < GG; i++) {
        const int v = is32 ? __ldg(&p32[i]) : (int)__ldg(&p64[i]);
        if (i < g) st += v;
        if (i == g) sz = v;
    }
    start = st; size = sz;
}

// Sum / sumsq over nv float4, 4-wide batched.
__device__ __forceinline__ void stats_range(const float4* __restrict__ px, int nv,
                                            float& s_out, float& ss_out) {
    float s = 0.f, ss = 0.f;
    int i = threadIdx.x;
    #pragma unroll 1
    for (; i + 3 * TPB < nv; i += 4 * TPB) {
        float4 v[4];
        #pragma unroll
        for (int u = 0; u < 4; u++) v[u] = px[i + u * TPB];
        #pragma unroll
        for (int u = 0; u < 4; u++) {
            s  += (v[u].x + v[u].y) + (v[u].z + v[u].w);
            ss += v[u].x * v[u].x + v[u].y * v[u].y
                + v[u].z * v[u].z + v[u].w * v[u].w;
        }
    }
    #pragma unroll 1
    for (; i < nv; i += TPB) {
        const float4 v = px[i];
        s  += (v.x + v.y) + (v.z + v.w);
        ss += v.x * v.x + v.y * v.y + v.z * v.z + v.w * v.w;
    }
    s_out = s; ss_out = ss;
}

// y = x*sc + sf over nv float4; pass-2 reads are L2-resident, dead after use.
__device__ __forceinline__ void apply_range(const float4* __restrict__ px,
                                            float4* __restrict__ po, int nv,
                                            float sc, float sf) {
    int i = threadIdx.x;
    #pragma unroll 1
    for (; i + 3 * TPB < nv; i += 4 * TPB) {
        float4 v[4];
        #pragma unroll
        for (int u = 0; u < 4; u++) v[u] = __ldcs(px + i + u * TPB);
        #pragma unroll
        for (int u = 0; u < 4; u++) {
            v[u].x = fmaf(v[u].x, sc, sf);
            v[u].y = fmaf(v[u].y, sc, sf);
            v[u].z = fmaf(v[u].z, sc, sf);
            v[u].w = fmaf(v[u].w, sc, sf);
            __stcs(po + i + u * TPB, v[u]);
        }
    }
    #pragma unroll 1
    for (; i < nv; i += TPB) {
        float4 v = __ldcs(px + i);
        v.x = fmaf(v.x, sc, sf);
        v.y = fmaf(v.y, sc, sf);
        v.z = fmaf(v.z, sc, sf);
        v.w = fmaf(v.w, sc, sf);
        __stcs(po + i, v);
    }
}

__device__ __forceinline__ float2 make_prm(float ts, float tss, int cnt,
                                           float gam, float bet) {
    const float inv  = 1.0f / (float)cnt;
    const float mean = ts * inv;
    const float var  = tss * inv - mean * mean;
    const float sc   = gam * rsqrtf(var + VGN_EPS);
    return make_float2(sc, fmaf(-mean, sc, bet));
}

// Block-reduce one (s,ss) pair -> (scale, shift).
__device__ __forceinline__ float2 finalize1(float s, float ss, int g, int cnt,
                                            const float* __restrict__ gamma,
                                            const float* __restrict__ beta) {
    #pragma unroll
    for (int o = 16; o > 0; o >>= 1) {
        s  += __shfl_xor_sync(0xFFFFFFFFu, s,  o);
        ss += __shfl_xor_sync(0xFFFFFFFFu, ss, o);
    }
    __shared__ float2 shw1[NWARP];
    __shared__ float2 sh_prm1;
    const int wid = threadIdx.x >> 5, lid = threadIdx.x & 31;
    if (lid == 0) shw1[wid] = make_float2(s, ss);
    __syncthreads();
    if (threadIdx.x == 0) {
        float ts = 0.f, tss = 0.f;
        #pragma unroll
        for (int w = 0; w < NWARP; w++) { ts += shw1[w].x; tss += shw1[w].y; }
        sh_prm1 = make_prm(ts, tss, cnt, __ldg(&gamma[g]), __ldg(&beta[g]));
    }
    __syncthreads();
    return sh_prm1;
}

// Block-reduce two (s,ss) pairs -> two (scale, shift).
__device__ __forceinline__ void finalize2(float s0, float ss0, float s1, float ss1,
                                          int g0, int n0, int g1, int n1,
                                          const float* __restrict__ gamma,
                                          const float* __restrict__ beta,
                                          float2& prm0, float2& prm1) {
    #pragma unroll
    for (int o = 16; o > 0; o >>= 1) {
        s0  += __shfl_xor_sync(0xFFFFFFFFu, s0,  o);
        ss0 += __shfl_xor_sync(0xFFFFFFFFu, ss0, o);
        s1  += __shfl_xor_sync(0xFFFFFFFFu, s1,  o);
        ss1 += __shfl_xor_sync(0xFFFFFFFFu, ss1, o);
    }
    __shared__ float4 shw2[NWARP];
    __shared__ float4 sh_prm2;
    const int wid = threadIdx.x >> 5, lid = threadIdx.x & 31;
    if (lid == 0) shw2[wid] = make_float4(s0, ss0, s1, ss1);
    __syncthreads();
    if (threadIdx.x == 0) {
        float t0 = 0.f, u0 = 0.f, t1 = 0.f, u1 = 0.f;
        #pragma unroll
        for (int w = 0; w < NWARP; w++) {
            t0 += shw2[w].x; u0 += shw2[w].y;
            t1 += shw2[w].z; u1 += shw2[w].w;
        }
        const float2 a = make_prm(t0, u0, n0, __ldg(&gamma[g0]), __ldg(&beta[g0]));
        const float2 b = make_prm(t1, u1, n1, __ldg(&gamma[g1]), __ldg(&beta[g1]));
        sh_prm2 = make_float4(a.x, a.y, b.x, b.y);
    }
    __syncthreads();
    prm0 = make_float2(sh_prm2.x, sh_prm2.y);
    prm1 = make_float2(sh_prm2.z, sh_prm2.w);
}

__global__ void __launch_bounds__(TPB, 6)
vgn_kernel(const float* __restrict__ x,
           const float* __restrict__ gamma,
           const float* __restrict__ beta,
           float* __restrict__ out,
           const void* __restrict__ gs_raw) {
    const int b = blockIdx.x;               // 0..767
    const int n = b & (NB - 1);
    const int j = b >> 5;                   // 0..23

    if (j < 16) {
        // ---- big CTA: one 12-channel (odd) group ----
        const int g = 2 * j + 1;
        int c0, gs;
        decode_group(gs_raw, g, c0, gs);
        const size_t base = ((size_t)n * CC + (size_t)c0) * HW;
        const float4* px = (const float4*)(x + base);
        float4* po       = (float4*)(out + base);
        const int nv = gs * HW4;

        float s, ss;
        stats_range(px, nv, s, ss);
        const float2 prm = finalize1(s, ss, g, gs * HW, gamma, beta);
        apply_range(px, po, nv, prm.x, prm.y);
    } else {
        // ---- small CTA: two 4-channel (even) groups: 4k and 4k+2 ----
        const int k = j - 16;               // 0..7
        const int g0 = 4 * k, g1 = 4 * k + 2;
        int c00, gs0, c01, gs1;
        decode_group(gs_raw, g0, c00, gs0);
        decode_group(gs_raw, g1, c01, gs1);
        const size_t base0 = ((size_t)n * CC + (size_t)c00) * HW;
        const size_t base1 = ((size_t)n * CC + (size_t)c01) * HW;
        const float4* px0 = (const float4*)(x + base0);
        const float4* px1 = (const float4*)(x + base1);
        float4* po0       = (float4*)(out + base0);
        float4* po1       = (float4*)(out + base1);
        const int nv0 = gs0 * HW4;
        const int nv1 = gs1 * HW4;

        float s0, ss0, s1, ss1;
        stats_range(px0, nv0, s0, ss0);
        stats_range(px1, nv1, s1, ss1);
        float2 prm0, prm1;
        finalize2(s0, ss0, s1, ss1, g0, gs0 * HW, g1, gs1 * HW,
                  gamma, beta, prm0, prm1);
        apply_range(px0, po0, nv0, prm0.x, prm0.y);
        apply_range(px1, po1, nv1, prm1.x, prm1.y);
    }
}

extern "C" void kernel_launch(void* const* d_in, const int* in_sizes, int n_in,
                              void* d_out, int out_size) {
    const float* x     = (const float*)d_in[0];
    const float* gamma = (const float*)d_in[1];
    const float* beta  = (const float*)d_in[2];
    const void*  gsz   = d_in[3];
    float* out = (float*)d_out;

    vgn_kernel<<<NB * 24, TPB>>>(x, gamma, beta, out, gsz);
}

// round 11
// speedup vs baseline: 1.3561x; 1.2768x over previous
#include <cuda_runtime.h>
#include <cstdint>

// VariableGroupNorm: x[N,C,H,W] fp32, ragged groups (channels contiguous per group).
// N=32, C=256, H=W=56, G=32. Sizes alternate 4/12 (even small, odd big).
// One CTA per (n, group); big groups scheduled first, small groups pack the tail.
// Occupancy capped at 3 CTAs/SM so the resident pass1->pass2 reuse window
// (~65 MB) stays inside the ~126 MB L2: pass-2 reads hit L2, DRAM sees x once.

#define NB 32
#define CC 256
#define GG 32
#define HW 3136                 // 56*56
#define HW4 784                 // float4 per channel
#define VGN_EPS 1e-5f
#define TPB 256
#define NWARP (TPB / 32)

// Decode group start/size table (int32 or int64, defensively).
__device__ __forceinline__ int2 vgn_decode_group(const void* __restrict__ gs_raw,
                                                 int g) {
    const int* p32 = (const int*)gs_raw;
    long long s32 = 0;
    #pragma unroll
    for (int i = 0; i < GG; i++) s32 += __ldg(&p32[i]);
    const bool is32 = (s32 == (long long)CC);
    const long long* p64 = (const long long*)gs_raw;
    int st = 0, sz = 0;
    #pragma unroll
    for (int i = 0; i < GG; i++) {
        const int v = is32 ? __ldg(&p32[i]) : (int)__ldg(&p64[i]);
        if (i < g) st += v;
        if (i == g) sz = v;
    }
    return make_int2(st, sz);
}

__global__ void __launch_bounds__(TPB, 3)
vgn_balanced_kernel(const float* __restrict__ x,
                    const float* __restrict__ gamma,
                    const float* __restrict__ beta,
                    float* __restrict__ out,
                    const void* __restrict__ gs_raw) {
    const int b = blockIdx.x;               // 0..1023
    const int half = b >> 9;                // 0 = big (odd) groups, 1 = small (even)
    const int idx = b & 511;
    const int n = idx & (NB - 1);
    const int k = idx >> 5;                 // 0..15
    const int g = 2 * k + 1 - half;

    const int2 cg = vgn_decode_group(gs_raw, g);
    const int c0 = cg.x;
    const int gs = cg.y;

    const size_t base = ((size_t)n * CC + (size_t)c0) * HW;
    const float4* __restrict__ px = (const float4*)(x + base);
    float4* __restrict__ po       = (float4*)(out + base);
    const int nv = gs * HW4;

    // ---- pass 1: sum / sumsq (default loads fill L2) ----
    float s = 0.f, ss = 0.f;
    {
        int i = threadIdx.x;
        #pragma unroll 1
        for (; i + 3 * TPB < nv; i += 4 * TPB) {
            float4 v0 = px[i];
            float4 v1 = px[i + TPB];
            float4 v2 = px[i + 2 * TPB];
            float4 v3 = px[i + 3 * TPB];
            s  += (v0.x + v0.y) + (v0.z + v0.w);
            ss += v0.x * v0.x + v0.y * v0.y + v0.z * v0.z + v0.w * v0.w;
            s  += (v1.x + v1.y) + (v1.z + v1.w);
            ss += v1.x * v1.x + v1.y * v1.y + v1.z * v1.z + v1.w * v1.w;
            s  += (v2.x + v2.y) + (v2.z + v2.w);
            ss += v2.x * v2.x + v2.y * v2.y + v2.z * v2.z + v2.w * v2.w;
            s  += (v3.x + v3.y) + (v3.z + v3.w);
            ss += v3.x * v3.x + v3.y * v3.y + v3.z * v3.z + v3.w * v3.w;
        }
        #pragma unroll 1
        for (; i < nv; i += TPB) {
            const float4 v = px[i];
            s  += (v.x + v.y) + (v.z + v.w);
            ss += v.x * v.x + v.y * v.y + v.z * v.z + v.w * v.w;
        }
    }

    // ---- block reduce -> scale/shift ----
    #pragma unroll
    for (int o = 16; o > 0; o >>= 1) {
        s  += __shfl_xor_sync(0xFFFFFFFFu, s,  o);
        ss += __shfl_xor_sync(0xFFFFFFFFu, ss, o);
    }
    __shared__ float2 shw[NWARP];
    __shared__ float2 sh_prm;
    const int wid = threadIdx.x >> 5;
    const int lid = threadIdx.x & 31;
    if (lid == 0) shw[wid] = make_float2(s, ss);
    __syncthreads();
    if (threadIdx.x == 0) {
        float ts = 0.f, tss = 0.f;
        #pragma unroll
        for (int w = 0; w < NWARP; w++) { ts += shw[w].x; tss += shw[w].y; }
        const float inv   = 1.0f / (float)(gs * HW);
        const float mean  = ts * inv;
        const float var   = tss * inv - mean * mean;
        const float sc    = __ldg(&gamma[g]) * rsqrtf(var + VGN_EPS);
        sh_prm = make_float2(sc, fmaf(-mean, sc, __ldg(&beta[g])));
    }
    __syncthreads();
    const float sc = sh_prm.x;
    const float sf = sh_prm.y;

    // ---- pass 2: normalize (L2-resident reads, dead after use; evict-first stores) ----
    {
        int i = threadIdx.x;
        #pragma unroll 1
        for (; i + 3 * TPB < nv; i += 4 * TPB) {
            float4 v0 = __ldcs(px + i);
            float4 v1 = __ldcs(px + i + TPB);
            float4 v2 = __ldcs(px + i + 2 * TPB);
            float4 v3 = __ldcs(px + i + 3 * TPB);
            v0.x = fmaf(v0.x, sc, sf); v0.y = fmaf(v0.y, sc, sf);
            v0.z = fmaf(v0.z, sc, sf); v0.w = fmaf(v0.w, sc, sf);
            v1.x = fmaf(v1.x, sc, sf); v1.y = fmaf(v1.y, sc, sf);
            v1.z = fmaf(v1.z, sc, sf); v1.w = fmaf(v1.w, sc, sf);
            v2.x = fmaf(v2.x, sc, sf); v2.y = fmaf(v2.y, sc, sf);
            v2.z = fmaf(v2.z, sc, sf); v2.w = fmaf(v2.w, sc, sf);
            v3.x = fmaf(v3.x, sc, sf); v3.y = fmaf(v3.y, sc, sf);
            v3.z = fmaf(v3.z, sc, sf); v3.w = fmaf(v3.w, sc, sf);
            __stcs(po + i, v0);
            __stcs(po + i + TPB, v1);
            __stcs(po + i + 2 * TPB, v2);
            __stcs(po + i + 3 * TPB, v3);
        }
        #pragma unroll 1
        for (; i < nv; i += TPB) {
            float4 v = __ldcs(px + i);
            v.x = fmaf(v.x, sc, sf);
            v.y = fmaf(v.y, sc, sf);
            v.z = fmaf(v.z, sc, sf);
            v.w = fmaf(v.w, sc, sf);
            __stcs(po + i, v);
        }
    }
}

extern "C" void kernel_launch(void* const* d_in, const int* in_sizes, int n_in,
                              void* d_out, int out_size) {
    const float* x     = (const float*)d_in[0];
    const float* gamma = (const float*)d_in[1];
    const float* beta  = (const float*)d_in[2];
    const void*  gsz   = d_in[3];
    float* out = (float*)d_out;

    vgn_balanced_kernel<<<NB * GG, TPB>>>(x, gamma, beta, out, gsz);
}

// round 12
// speedup vs baseline: 1.4429x; 1.0640x over previous
#include <cuda_runtime.h>
#include <cstdint>

// VariableGroupNorm: x[N,C,H,W] fp32, ragged groups (channels contiguous per group).
// N=32, C=256, H=W=56, G=32. Group starts are multiples of 4 (sizes alternate 4/12),
// so a 4-channel chunk never crosses a group boundary. 2048 uniform CTAs, one per
// (n, chunk). Multi-chunk groups (12-ch = 3 adjacent CTAs) rendezvous their stats
// through L2 atomics; accumulators are reset to zero by the last reader so every
// graph replay starts from clean state.

#define NB 32
#define CC 256
#define GG 32
#define HW 3136                 // 56*56
#define CHUNK_CH 4
#define CHUNKS_PER_N (CC / CHUNK_CH)   // 64
#define NV (CHUNK_CH * HW / 4)  // float4 per chunk = 3136
#define VGN_EPS 1e-5f
#define TPB 256
#define NWARP (TPB / 32)

// Rendezvous state, one slot per (n, group). Zero-initialized at module load;
// the protocol below leaves every touched slot zeroed at kernel exit.
__device__ float d_accS[NB * GG];
__device__ float d_accQ[NB * GG];
__device__ int   d_cnt[NB * GG];
__device__ int   d_done[NB * GG];

// Decode: for chunk starting at channel c0 -> group id, #chunks in group, gsize.
__device__ __forceinline__ void decode_for_chunk(const void* __restrict__ gs_raw,
                                                 int c0, int& g, int& nch,
                                                 int& gsize) {
    const int* p32 = (const int*)gs_raw;
    long long s32 = 0;
    #pragma unroll
    for (int i = 0; i < GG; i++) s32 += __ldg(&p32[i]);
    const bool is32 = (s32 == (long long)CC);
    const long long* p64 = (const long long*)gs_raw;
    int start = 0;
    g = 0; nch = 1; gsize = CHUNK_CH;
    #pragma unroll
    for (int i = 0; i < GG; i++) {
        const int sz = is32 ? __ldg(&p32[i]) : (int)__ldg(&p64[i]);
        if (c0 >= start && c0 < start + sz) {
            g = i;
            gsize = sz;
            nch = sz / CHUNK_CH;
        }
        start += sz;
    }
}

__global__ void __launch_bounds__(TPB)
vgn_rendezvous_kernel(const float* __restrict__ x,
                      const float* __restrict__ gamma,
                      const float* __restrict__ beta,
                      float* __restrict__ out,
                      const void* __restrict__ gs_raw) {
    const int b = blockIdx.x;            // 0..2047; siblings of a group are adjacent
    const int n = b >> 6;
    const int ck = b & (CHUNKS_PER_N - 1);
    const int c0 = ck * CHUNK_CH;

    const size_t base = ((size_t)n * CC + (size_t)c0) * HW;
    const float4* __restrict__ px = (const float4*)(x + base);
    float4* __restrict__ po       = (float4*)(out + base);

    // ---- pass 1: chunk sum / sumsq ----
    float s = 0.f, ss = 0.f;
    {
        int i = threadIdx.x;
        #pragma unroll 1
        for (; i + 3 * TPB < NV; i += 4 * TPB) {
            float4 v0 = px[i];
            float4 v1 = px[i + TPB];
            float4 v2 = px[i + 2 * TPB];
            float4 v3 = px[i + 3 * TPB];
            s  += (v0.x + v0.y) + (v0.z + v0.w);
            ss += v0.x * v0.x + v0.y * v0.y + v0.z * v0.z + v0.w * v0.w;
            s  += (v1.x + v1.y) + (v1.z + v1.w);
            ss += v1.x * v1.x + v1.y * v1.y + v1.z * v1.z + v1.w * v1.w;
            s  += (v2.x + v2.y) + (v2.z + v2.w);
            ss += v2.x * v2.x + v2.y * v2.y + v2.z * v2.z + v2.w * v2.w;
            s  += (v3.x + v3.y) + (v3.z + v3.w);
            ss += v3.x * v3.x + v3.y * v3.y + v3.z * v3.z + v3.w * v3.w;
        }
        if (i < NV) {                    // NV = 12*TPB + 64: one predicated tail
            const float4 v = px[i];
            s  += (v.x + v.y) + (v.z + v.w);
            ss += v.x * v.x + v.y * v.y + v.z * v.z + v.w * v.w;
        }
    }

    #pragma unroll
    for (int o = 16; o > 0; o >>= 1) {
        s  += __shfl_xor_sync(0xFFFFFFFFu, s,  o);
        ss += __shfl_xor_sync(0xFFFFFFFFu, ss, o);
    }
    __shared__ float2 shw[NWARP];
    __shared__ float2 sh_prm;
    const int wid = threadIdx.x >> 5, lid = threadIdx.x & 31;
    if (lid == 0) shw[wid] = make_float2(s, ss);
    __syncthreads();

    if (threadIdx.x == 0) {
        float ts = 0.f, tss = 0.f;
        #pragma unroll
        for (int w = 0; w < NWARP; w++) { ts += shw[w].x; tss += shw[w].y; }

        int g, nch, gsize;
        decode_for_chunk(gs_raw, c0, g, nch, gsize);

        if (nch > 1) {
            // ---- rendezvous with sibling chunks (adjacent CTAs) ----
            const int id = n * GG + g;
            atomicAdd(&d_accS[id], ts);
            atomicAdd(&d_accQ[id], tss);
            __threadfence();
            atomicAdd(&d_cnt[id], 1);
            while (atomicAdd(&d_cnt[id], 0) < nch) { __nanosleep(64); }
            __threadfence();
            ts  = atomicAdd(&d_accS[id], 0.0f);
            tss = atomicAdd(&d_accQ[id], 0.0f);
            // Last reader resets the slot to zero for the next replay.
            const int d = atomicAdd(&d_done[id], 1);
            if (d == nch - 1) {
                atomicExch(&d_accS[id], 0.0f);
                atomicExch(&d_accQ[id], 0.0f);
                atomicExch(&d_cnt[id], 0);
                atomicExch(&d_done[id], 0);
            }
        }

        const float inv   = 1.0f / (float)(gsize * HW);
        const float mean  = ts * inv;
        const float var   = tss * inv - mean * mean;
        const float sc    = __ldg(&gamma[g]) * rsqrtf(var + VGN_EPS);
        sh_prm = make_float2(sc, fmaf(-mean, sc, __ldg(&beta[g])));
    }
    __syncthreads();
    const float sc = sh_prm.x;
    const float sf = sh_prm.y;

    // ---- pass 2: normalize (reads L2-resident, dead after use; evict-first stores) ----
    {
        int i = threadIdx.x;
        #pragma unroll 1
        for (; i + 3 * TPB < NV; i += 4 * TPB) {
            float4 v0 = __ldcs(px + i);
            float4 v1 = __ldcs(px + i + TPB);
            float4 v2 = __ldcs(px + i + 2 * TPB);
            float4 v3 = __ldcs(px + i + 3 * TPB);
            v0.x = fmaf(v0.x, sc, sf); v0.y = fmaf(v0.y, sc, sf);
            v0.z = fmaf(v0.z, sc, sf); v0.w = fmaf(v0.w, sc, sf);
            v1.x = fmaf(v1.x, sc, sf); v1.y = fmaf(v1.y, sc, sf);
            v1.z = fmaf(v1.z, sc, sf); v1.w = fmaf(v1.w, sc, sf);
            v2.x = fmaf(v2.x, sc, sf); v2.y = fmaf(v2.y, sc, sf);
            v2.z = fmaf(v2.z, sc, sf); v2.w = fmaf(v2.w, sc, sf);
            v3.x = fmaf(v3.x, sc, sf); v3.y = fmaf(v3.y, sc, sf);
            v3.z = fmaf(v3.z, sc, sf); v3.w = fmaf(v3.w, sc, sf);
            __stcs(po + i, v0);
            __stcs(po + i + TPB, v1);
            __stcs(po + i + 2 * TPB, v2);
            __stcs(po + i + 3 * TPB, v3);
        }
        if (i < NV) {
            float4 v = __ldcs(px + i);
            v.x = fmaf(v.x, sc, sf);
            v.y = fmaf(v.y, sc, sf);
            v.z = fmaf(v.z, sc, sf);
            v.w = fmaf(v.w, sc, sf);
            __stcs(po + i, v);
        }
    }
}

extern "C" void kernel_launch(void* const* d_in, const int* in_sizes, int n_in,
                              void* d_out, int out_size) {
    const float* x     = (const float*)d_in[0];
    const float* gamma = (const float*)d_in[1];
    const float* beta  = (const float*)d_in[2];
    const void*  gsz   = d_in[3];
    float* out = (float*)d_out;

    vgn_rendezvous_kernel<<<NB * CHUNKS_PER_N, TPB>>>(x, gamma, beta, out, gsz);
}